// round 1
// baseline (speedup 1.0000x reference)
#include <cuda_runtime.h>
#include <cstdint>

// Problem constants
#define Bb  2
#define Ss  2048
#define Dd  1024
#define Hh  16
#define HDd 64
#define MS  (Bb*Ss)          // 4096 rows
#define LN_EPS 1e-5f

// ---------------------------------------------------------------------------
// Scratch (device globals -- no allocation allowed in kernel_launch)
// ---------------------------------------------------------------------------
__device__ float g_q[MS*Dd];     // Q projection  [B*S, D]
__device__ float g_k[MS*Dd];     // K projection
__device__ float g_v[MS*Dd];     // V projection
__device__ float g_att[MS*Dd];   // attention output (head-concat layout)
__device__ float g_tmp[MS*Dd];   // output proj + residual (pre-LN)

// ---------------------------------------------------------------------------
// SGEMM: C[M,N] = A[M,K] @ B[K,N] (+ resid). 128x128 block tile, BK=16,
// 256 threads, 8x8 per-thread as 2x2 blocks of 4x4 (interleave 64) so all
// shared-memory compute loads are float4 and conflict-free.
// Requires M%128==0, N%128==0, K%16==0.
// ---------------------------------------------------------------------------
__global__ __launch_bounds__(256) void sgemm128(
    const float* __restrict__ A, const float* __restrict__ Bm,
    const float* __restrict__ resid, float* __restrict__ C,
    int M, int N, int K)
{
    __shared__ float As[16][128];   // transposed A tile: As[k][m]
    __shared__ float Bs[16][128];   // Bs[k][n]

    const int tid = threadIdx.x;
    const int tx = tid & 15;        // 0..15 -> col groups
    const int ty = tid >> 4;        // 0..15 -> row groups
    const int bm = blockIdx.y * 128;
    const int bn = blockIdx.x * 128;

    float acc[2][2][4][4];
    #pragma unroll
    for (int ih = 0; ih < 2; ih++)
        #pragma unroll
        for (int jh = 0; jh < 2; jh++)
            #pragma unroll
            for (int i = 0; i < 4; i++)
                #pragma unroll
                for (int j = 0; j < 4; j++)
                    acc[ih][jh][i][j] = 0.f;

    for (int k0 = 0; k0 < K; k0 += 16) {
        // Load A tile (128x16) transposed, and B tile (16x128).
        #pragma unroll
        for (int it = 0; it < 2; it++) {
            int f = tid + (it << 8);                  // float4 index 0..511
            int ra = f >> 2;                          // A row 0..127
            int ca = (f & 3) << 2;                    // A col {0,4,8,12}
            float4 va = *(const float4*)(A + (size_t)(bm + ra) * K + k0 + ca);
            As[ca + 0][ra] = va.x;
            As[ca + 1][ra] = va.y;
            As[ca + 2][ra] = va.z;
            As[ca + 3][ra] = va.w;

            int rb = f >> 5;                          // B row 0..15
            int cb = (f & 31) << 2;                   // B col 0..124
            *(float4*)(&Bs[rb][cb]) =
                *(const float4*)(Bm + (size_t)(k0 + rb) * N + bn + cb);
        }
        __syncthreads();

        #pragma unroll
        for (int k = 0; k < 16; k++) {
            float ra[2][4], rb[2][4];
            #pragma unroll
            for (int ih = 0; ih < 2; ih++)
                *(float4*)ra[ih] = *(const float4*)(&As[k][ih * 64 + ty * 4]);
            #pragma unroll
            for (int jh = 0; jh < 2; jh++)
                *(float4*)rb[jh] = *(const float4*)(&Bs[k][jh * 64 + tx * 4]);
            #pragma unroll
            for (int ih = 0; ih < 2; ih++)
                #pragma unroll
                for (int jh = 0; jh < 2; jh++)
                    #pragma unroll
                    for (int i = 0; i < 4; i++)
                        #pragma unroll
                        for (int j = 0; j < 4; j++)
                            acc[ih][jh][i][j] += ra[ih][i] * rb[jh][j];
        }
        __syncthreads();
    }

    // Epilogue: optional residual add, float4 coalesced stores.
    #pragma unroll
    for (int ih = 0; ih < 2; ih++) {
        #pragma unroll
        for (int i = 0; i < 4; i++) {
            int row = bm + ih * 64 + ty * 4 + i;
            #pragma unroll
            for (int jh = 0; jh < 2; jh++) {
                int col = bn + jh * 64 + tx * 4;
                float4 o;
                o.x = acc[ih][jh][i][0];
                o.y = acc[ih][jh][i][1];
                o.z = acc[ih][jh][i][2];
                o.w = acc[ih][jh][i][3];
                if (resid) {
                    float4 rr = *(const float4*)(resid + (size_t)row * N + col);
                    o.x += rr.x; o.y += rr.y; o.z += rr.z; o.w += rr.w;
                }
                *(float4*)(C + (size_t)row * N + col) = o;
            }
        }
    }
}

// ---------------------------------------------------------------------------
// Causal flash attention, fp32, online softmax.
// One block per (q-tile of 64, head, batch). 256 threads = 16x16 grid,
// each thread owns a 4x4 patch of the 64x64 score / output tile.
// Shared: Qs[64][64], KPs[64][65] (K tile, then reused for P), Vs[64][64].
// ---------------------------------------------------------------------------
#define ATTN_SMEM ((64*64 + 64*65 + 64*64) * 4)

__global__ __launch_bounds__(256) void attn_kernel(
    const float* __restrict__ Qp, const float* __restrict__ Kp,
    const float* __restrict__ Vp, float* __restrict__ Op)
{
    extern __shared__ float sm[];
    float* Qs  = sm;                 // [64][64]
    float* KPs = sm + 64 * 64;       // [64][65]  K: [kpos][d]; later P: [qrow][kcol]
    float* Vs  = KPs + 64 * 65;      // [64][64]  [kpos][d]

    const int tid = threadIdx.x;
    const int tx = tid & 15;
    const int ty = tid >> 4;
    const int qt = blockIdx.x;
    const int h  = blockIdx.y;
    const int b  = blockIdx.z;
    const int q0 = qt * 64;

    const float* Qb = Qp + (size_t)b * Ss * Dd + h * HDd;
    const float* Kb = Kp + (size_t)b * Ss * Dd + h * HDd;
    const float* Vb = Vp + (size_t)b * Ss * Dd + h * HDd;

    // Load Q tile (64 rows x 64 dims), float4, conflict-free.
    #pragma unroll
    for (int it = 0; it < 4; it++) {
        int f = tid + (it << 8);          // float4 index 0..1023
        int r = f >> 4;
        int c = (f & 15) << 2;
        *(float4*)(&Qs[r * 64 + c]) =
            *(const float4*)(Qb + (size_t)(q0 + r) * Dd + c);
    }

    float m_[4], l_[4], acc[4][4];
    #pragma unroll
    for (int i = 0; i < 4; i++) {
        m_[i] = -1e30f;
        l_[i] = 0.f;
        #pragma unroll
        for (int j = 0; j < 4; j++) acc[i][j] = 0.f;
    }

    for (int kt = 0; kt <= qt; kt++) {
        const int k0 = kt * 64;
        __syncthreads();   // previous iteration's P/V reads complete (also covers Qs fill)

        // Load K tile (scalar stores, pitch 65) and V tile (float4, pitch 64).
        #pragma unroll
        for (int it = 0; it < 4; it++) {
            int f = tid + (it << 8);
            int r = f >> 4;
            int c = (f & 15) << 2;
            float4 kv = *(const float4*)(Kb + (size_t)(k0 + r) * Dd + c);
            KPs[r * 65 + c + 0] = kv.x;
            KPs[r * 65 + c + 1] = kv.y;
            KPs[r * 65 + c + 2] = kv.z;
            KPs[r * 65 + c + 3] = kv.w;
            *(float4*)(&Vs[r * 64 + c]) =
                *(const float4*)(Vb + (size_t)(k0 + r) * Dd + c);
        }
        __syncthreads();

        // S = Q K^T (4x4 patch per thread)
        float s[4][4];
        #pragma unroll
        for (int i = 0; i < 4; i++)
            #pragma unroll
            for (int j = 0; j < 4; j++) s[i][j] = 0.f;

        #pragma unroll 8
        for (int d = 0; d < 64; d++) {
            float qa[4], kb[4];
            #pragma unroll
            for (int i = 0; i < 4; i++) qa[i] = Qs[(ty * 4 + i) * 64 + d];
            #pragma unroll
            for (int j = 0; j < 4; j++) kb[j] = KPs[(tx * 4 + j) * 65 + d];
            #pragma unroll
            for (int i = 0; i < 4; i++)
                #pragma unroll
                for (int j = 0; j < 4; j++)
                    s[i][j] += qa[i] * kb[j];
        }

        const bool diag = (kt == qt);
        #pragma unroll
        for (int i = 0; i < 4; i++)
            #pragma unroll
            for (int j = 0; j < 4; j++) {
                s[i][j] *= 0.125f;   // 1/sqrt(64)
                if (diag && (tx * 4 + j) > (ty * 4 + i)) s[i][j] = -1e30f;
            }

        // Online softmax update (row reductions across the 16 tx lanes,
        // which form a contiguous half-warp -> xor-shuffles of 1,2,4,8).
        float p[4][4];
        #pragma unroll
        for (int i = 0; i < 4; i++) {
            float mx = fmaxf(fmaxf(s[i][0], s[i][1]), fmaxf(s[i][2], s[i][3]));
            #pragma unroll
            for (int o = 8; o > 0; o >>= 1)
                mx = fmaxf(mx, __shfl_xor_sync(0xffffffffu, mx, o));
            float mn = fmaxf(m_[i], mx);
            float sum = 0.f;
            #pragma unroll
            for (int j = 0; j < 4; j++) {
                p[i][j] = __expf(s[i][j] - mn);
                sum += p[i][j];
            }
            #pragma unroll
            for (int o = 8; o > 0; o >>= 1)
                sum += __shfl_xor_sync(0xffffffffu, sum, o);
            float corr = __expf(m_[i] - mn);
            l_[i] = l_[i] * corr + sum;
            m_[i] = mn;
            #pragma unroll
            for (int j = 0; j < 4; j++) acc[i][j] *= corr;
        }

        __syncthreads();   // everyone done reading K from KPs
        #pragma unroll
        for (int i = 0; i < 4; i++)
            #pragma unroll
            for (int j = 0; j < 4; j++)
                KPs[(ty * 4 + i) * 65 + tx * 4 + j] = p[i][j];
        __syncthreads();

        // acc += P @ V
        #pragma unroll 8
        for (int kk = 0; kk < 64; kk++) {
            float pa[4], vv[4];
            #pragma unroll
            for (int i = 0; i < 4; i++) pa[i] = KPs[(ty * 4 + i) * 65 + kk];
            #pragma unroll
            for (int j = 0; j < 4; j++) vv[j] = Vs[kk * 64 + tx * 4 + j];
            #pragma unroll
            for (int i = 0; i < 4; i++)
                #pragma unroll
                for (int j = 0; j < 4; j++)
                    acc[i][j] += pa[i] * vv[j];
        }
    }

    // Normalize and write (head-concat layout [B*S, D]).
    float* Ob = Op + (size_t)b * Ss * Dd + h * HDd;
    #pragma unroll
    for (int i = 0; i < 4; i++) {
        float inv = 1.0f / l_[i];
        float4 o;
        o.x = acc[i][0] * inv;
        o.y = acc[i][1] * inv;
        o.z = acc[i][2] * inv;
        o.w = acc[i][3] * inv;
        *(float4*)(Ob + (size_t)(q0 + ty * 4 + i) * Dd + tx * 4) = o;
    }
}

// ---------------------------------------------------------------------------
// LayerNorm over last dim (1024), one block (256 threads) per row.
// ---------------------------------------------------------------------------
__global__ __launch_bounds__(256) void ln_kernel(
    const float* __restrict__ X, const float* __restrict__ gamma,
    const float* __restrict__ beta, float* __restrict__ Y)
{
    const int row = blockIdx.x;
    const int t = threadIdx.x;
    const float4 v = ((const float4*)(X + (size_t)row * Dd))[t];

    float s  = v.x + v.y + v.z + v.w;
    float ss = v.x * v.x + v.y * v.y + v.z * v.z + v.w * v.w;
    #pragma unroll
    for (int o = 16; o > 0; o >>= 1) {
        s  += __shfl_xor_sync(0xffffffffu, s,  o);
        ss += __shfl_xor_sync(0xffffffffu, ss, o);
    }
    __shared__ float sh[8][2];
    if ((t & 31) == 0) { sh[t >> 5][0] = s; sh[t >> 5][1] = ss; }
    __syncthreads();
    float ts = 0.f, tss = 0.f;
    #pragma unroll
    for (int i = 0; i < 8; i++) { ts += sh[i][0]; tss += sh[i][1]; }

    const float mu  = ts * (1.0f / Dd);
    const float var = tss * (1.0f / Dd) - mu * mu;
    const float inv = rsqrtf(var + LN_EPS);

    const float4 gg = ((const float4*)gamma)[t];
    const float4 bb = ((const float4*)beta)[t];
    float4 y;
    y.x = (v.x - mu) * inv * gg.x + bb.x;
    y.y = (v.y - mu) * inv * gg.y + bb.y;
    y.z = (v.z - mu) * inv * gg.z + bb.z;
    y.w = (v.w - mu) * inv * gg.w + bb.w;
    ((float4*)(Y + (size_t)row * Dd))[t] = y;
}

// ---------------------------------------------------------------------------
// Launch. Inputs (metadata order): q, k, v, wq, wk, wv, wo, gamma, beta, mask.
// The mask is the fixed causal mask (reference constructs it as such), so it
// is applied analytically in attn_kernel and the tensor itself is unused.
// ---------------------------------------------------------------------------
extern "C" void kernel_launch(void* const* d_in, const int* in_sizes, int n_in,
                              void* d_out, int out_size)
{
    const float* q     = (const float*)d_in[0];
    const float* k     = (const float*)d_in[1];
    const float* v     = (const float*)d_in[2];
    const float* wq    = (const float*)d_in[3];
    const float* wk    = (const float*)d_in[4];
    const float* wv    = (const float*)d_in[5];
    const float* wo    = (const float*)d_in[6];
    const float* gamma = (const float*)d_in[7];
    const float* beta  = (const float*)d_in[8];
    float* out = (float*)d_out;

    float *gq, *gk, *gv, *gatt, *gtmp;
    cudaGetSymbolAddress((void**)&gq,   g_q);
    cudaGetSymbolAddress((void**)&gk,   g_k);
    cudaGetSymbolAddress((void**)&gv,   g_v);
    cudaGetSymbolAddress((void**)&gatt, g_att);
    cudaGetSymbolAddress((void**)&gtmp, g_tmp);

    cudaFuncSetAttribute(attn_kernel,
                         cudaFuncAttributeMaxDynamicSharedMemorySize, ATTN_SMEM);

    dim3 blk(256);
    dim3 gproj(Dd / 128, MS / 128);           // (8, 32)

    sgemm128<<<gproj, blk>>>(q, wq, nullptr, gq, MS, Dd, Dd);
    sgemm128<<<gproj, blk>>>(k, wk, nullptr, gk, MS, Dd, Dd);
    sgemm128<<<gproj, blk>>>(v, wv, nullptr, gv, MS, Dd, Dd);

    dim3 ga(Ss / 64, Hh, Bb);                 // (32, 16, 2)
    attn_kernel<<<ga, blk, ATTN_SMEM>>>(gq, gk, gv, gatt);

    sgemm128<<<gproj, blk>>>(gatt, wo, q, gtmp, MS, Dd, Dd);

    ln_kernel<<<MS, blk>>>(gtmp, gamma, beta, out);
}

// round 3
// speedup vs baseline: 1.5969x; 1.5969x over previous
#include <cuda_runtime.h>
#include <cuda_bf16.h>
#include <cstdint>

// Problem constants
#define Bb  2
#define Ss  2048
#define Dd  1024
#define Hh  16
#define HDd 64
#define MS  (Bb*Ss)          // 4096 rows
#define LN_EPS 1e-5f
#define GK 1024

// Feature gate: tcgen05 only exists on the arch-specific ('a') target.
#if defined(__CUDA_ARCH_FEAT_SM103_ALL)
#define USE_TC 1
#else
#define USE_TC 0
#endif

// ---------------------------------------------------------------------------
// Scratch (device globals -- no allocation allowed in kernel_launch)
// ---------------------------------------------------------------------------
__device__ float g_q[MS*Dd];
__device__ float g_k[MS*Dd];
__device__ float g_v[MS*Dd];
__device__ float g_att[MS*Dd];
__device__ float g_tmp[MS*Dd];
__device__ __nv_bfloat16 g_ah[MS*Dd];   // activation hi
__device__ __nv_bfloat16 g_al[MS*Dd];   // activation lo
__device__ __nv_bfloat16 g_wh[Dd*Dd];   // weight^T hi  [N][K]
__device__ __nv_bfloat16 g_wl[Dd*Dd];   // weight^T lo  [N][K]

// ---------------------------------------------------------------------------
// Common helpers (base-arch safe)
// ---------------------------------------------------------------------------
__device__ __forceinline__ uint32_t smem_u32(const void* p) {
    uint32_t a;
    asm("{ .reg .u64 t; cvta.to.shared.u64 t, %1; cvt.u32.u64 %0, t; }"
        : "=r"(a) : "l"(p));
    return a;
}

__device__ __forceinline__ void cpa16(uint32_t s, const void* g) {
    asm volatile("cp.async.cg.shared.global [%0], [%1], 16;" :: "r"(s), "l"(g));
}
#define CPA_COMMIT() asm volatile("cp.async.commit_group;" ::: "memory")
#define CPA_WAIT0()  asm volatile("cp.async.wait_group 0;" ::: "memory")

__device__ __forceinline__ void ldm4(uint32_t a, uint32_t r[4]) {
    asm volatile("ldmatrix.sync.aligned.m8n8.x4.shared.b16 {%0,%1,%2,%3}, [%4];"
                 : "=r"(r[0]), "=r"(r[1]), "=r"(r[2]), "=r"(r[3]) : "r"(a));
}
__device__ __forceinline__ void mma16816(float d[4], const uint32_t a[4],
                                         uint32_t b0, uint32_t b1) {
    asm volatile(
        "mma.sync.aligned.m16n8k16.row.col.f32.bf16.bf16.f32 "
        "{%0,%1,%2,%3}, {%4,%5,%6,%7}, {%8,%9}, {%0,%1,%2,%3};"
        : "+f"(d[0]), "+f"(d[1]), "+f"(d[2]), "+f"(d[3])
        : "r"(a[0]), "r"(a[1]), "r"(a[2]), "r"(a[3]), "r"(b0), "r"(b1));
}

#define GEMM_SMEM 81920

#if USE_TC
// ---------------------------------------------------------------------------
// tcgen05 helpers (only compiled on the 'a' pass)
// ---------------------------------------------------------------------------
__device__ __forceinline__ uint32_t elect1() {
    uint32_t p;
    asm volatile("{ .reg .pred p; elect.sync _|p, 0xFFFFFFFF; selp.b32 %0,1,0,p; }"
                 : "=r"(p));
    return p;
}
#define MBAR_INIT(a, c) \
    asm volatile("mbarrier.init.shared.b64 [%0], %1;" :: "r"(a), "r"(c) : "memory")
#define MBAR_INVAL(a) \
    asm volatile("mbarrier.inval.shared.b64 [%0];" :: "r"(a) : "memory")
__device__ __forceinline__ void mbar_wait(uint32_t addr, uint32_t parity) {
    asm volatile(
        "{\n\t.reg .pred P;\n\t"
        "WL_%=:\n\t"
        "mbarrier.try_wait.parity.acquire.cta.shared::cta.b64 P, [%0], %1, 0x989680;\n\t"
        "@P bra WD_%=;\n\t"
        "bra WL_%=;\n\t"
        "WD_%=:\n\t}"
        :: "r"(addr), "r"(parity) : "memory");
}
#define TC_ALLOC(sa, n) \
    asm volatile("tcgen05.alloc.cta_group::1.sync.aligned.shared::cta.b32 [%0], %1;" \
                 :: "r"(sa), "r"(n) : "memory")
#define TC_RELINQ() \
    asm volatile("tcgen05.relinquish_alloc_permit.cta_group::1.sync.aligned;")
#define TC_DEALLOC(t, n) \
    asm volatile("tcgen05.dealloc.cta_group::1.sync.aligned.b32 %0, %1;" :: "r"(t), "r"(n))
#define TC_COMMIT(mb) \
    asm volatile("tcgen05.commit.cta_group::1.mbarrier::arrive::one.shared::cluster.b64 [%0];" \
                 :: "r"(mb) : "memory")
#define TC_FENCE_AFTER()  asm volatile("tcgen05.fence::after_thread_sync;" ::: "memory")
#define TC_FENCE_BEFORE() asm volatile("tcgen05.fence::before_thread_sync;" ::: "memory")
#define TC_WAIT_LD()      asm volatile("tcgen05.wait::ld.sync.aligned;" ::: "memory")
#define FENCE_ASYNC()     asm volatile("fence.proxy.async.shared::cta;" ::: "memory")

#define TC_LD32(r, ta) \
    asm volatile( \
        "tcgen05.ld.sync.aligned.32x32b.x32.b32 " \
        "{%0, %1, %2, %3, %4, %5, %6, %7, " \
        " %8, %9, %10, %11, %12, %13, %14, %15, " \
        " %16, %17, %18, %19, %20, %21, %22, %23, " \
        " %24, %25, %26, %27, %28, %29, %30, %31}, [%32];" \
        : "=r"((r)[0]),  "=r"((r)[1]),  "=r"((r)[2]),  "=r"((r)[3]), \
          "=r"((r)[4]),  "=r"((r)[5]),  "=r"((r)[6]),  "=r"((r)[7]), \
          "=r"((r)[8]),  "=r"((r)[9]),  "=r"((r)[10]), "=r"((r)[11]), \
          "=r"((r)[12]), "=r"((r)[13]), "=r"((r)[14]), "=r"((r)[15]), \
          "=r"((r)[16]), "=r"((r)[17]), "=r"((r)[18]), "=r"((r)[19]), \
          "=r"((r)[20]), "=r"((r)[21]), "=r"((r)[22]), "=r"((r)[23]), \
          "=r"((r)[24]), "=r"((r)[25]), "=r"((r)[26]), "=r"((r)[27]), \
          "=r"((r)[28]), "=r"((r)[29]), "=r"((r)[30]), "=r"((r)[31]) \
        : "r"(ta))

__device__ __forceinline__ uint64_t mk_desc(uint32_t sa) {
    return ((uint64_t)2 << 61) | ((uint64_t)1 << 46) | ((uint64_t)64 << 32)
         | ((uint64_t)1 << 16) | (uint64_t)((sa >> 4) & 0x3FFF);
}
__device__ __forceinline__ void mma_f16_ss(uint32_t d, uint64_t a, uint64_t b,
                                           uint32_t idesc, uint32_t en) {
    asm volatile(
        "{\n\t.reg .pred p;\n\t"
        "setp.ne.u32 p, %4, 0;\n\t"
        "tcgen05.mma.cta_group::1.kind::f16 [%0], %1, %2, %3, {%5, %5, %5, %5}, p;\n\t"
        "}"
        :: "r"(d), "l"(a), "l"(b), "r"(idesc), "r"(en), "r"(0u)
        : "memory");
}
#define TCIDESC ((1u << 4) | (1u << 7) | (1u << 10) | ((128u / 8) << 17) | ((128u / 16) << 24))
#define TCTILE_B (128 * 64 * 2)   // 16384

__device__ __forceinline__ void tc_load_tile(char* dst, const __nv_bfloat16* src, int tid) {
    // 128 rows x 64 bf16 (128B rows), SW128 swizzle, 16B vectors.
    #pragma unroll
    for (int it = 0; it < 8; it++) {
        int f = tid + it * 128;
        int r = f >> 3;
        int u = f & 7;
        uint4 v = ((const uint4*)(src + (size_t)r * GK))[u];
        uint32_t off = (uint32_t)(r * 128 + u * 16);
        off ^= (off >> 3) & 0x70;
        *(uint4*)(dst + off) = v;
    }
}
#endif // USE_TC

// ---------------------------------------------------------------------------
// Tensor-core split-bf16 GEMM: C[4096,1024] = A @ W (+resid)
// A as (Ah, Al) row-major bf16; W transposed as (Wh, Wl) [N][K].
// Launch: grid (8, 32), 128 threads, GEMM_SMEM dynamic smem (both paths).
// ---------------------------------------------------------------------------
__global__ __launch_bounds__(128) __cluster_dims__(1, 1, 1)
void gemm_tc(const __nv_bfloat16* __restrict__ Ah, const __nv_bfloat16* __restrict__ Al,
             const __nv_bfloat16* __restrict__ Wh, const __nv_bfloat16* __restrict__ Wl,
             const float* __restrict__ resid, float* __restrict__ C)
{
#if USE_TC
    // ---------------- tcgen05 path: single-stage BK=64 ----------------
    extern __shared__ char smraw[];
    __shared__ uint32_t s_tptr[1];
    __shared__ __align__(8) uint64_t s_mbar[1];

    const int tid = threadIdx.x;
    const int wid = tid >> 5;
    const int lid = tid & 31;
    const int bm = blockIdx.y * 128;
    const int bn = blockIdx.x * 128;

    uint32_t smb0 = smem_u32(smraw);
    char* sm = smraw + (((smb0 + 1023u) & ~1023u) - smb0);
    uint32_t mb0 = smem_u32(&s_mbar[0]);

    if (wid == 0) { TC_ALLOC(smem_u32(s_tptr), 128); TC_RELINQ(); }
    if (tid == 0) MBAR_INIT(mb0, 1);
    __syncthreads();
    const uint32_t tmem = s_tptr[0];

    const __nv_bfloat16* srcA  = Ah + (size_t)bm * GK;
    const __nv_bfloat16* srcAl = Al + (size_t)bm * GK;
    const __nv_bfloat16* srcW  = Wh + (size_t)bn * GK;
    const __nv_bfloat16* srcWl = Wl + (size_t)bn * GK;

    for (int i = 0; i < 16; i++) {
        const int k0 = i * 64;
        tc_load_tile(sm,              srcA  + k0, tid);
        tc_load_tile(sm + TCTILE_B,   srcAl + k0, tid);
        tc_load_tile(sm + 2*TCTILE_B, srcW  + k0, tid);
        tc_load_tile(sm + 3*TCTILE_B, srcWl + k0, tid);
        FENCE_ASYNC();
        __syncthreads();

        if (wid == 0 && elect1()) {
            uint64_t dA  = mk_desc(smem_u32(sm));
            uint64_t dAl = mk_desc(smem_u32(sm + TCTILE_B));
            uint64_t dW  = mk_desc(smem_u32(sm + 2*TCTILE_B));
            uint64_t dWl = mk_desc(smem_u32(sm + 3*TCTILE_B));
            uint32_t en = (i == 0) ? 0u : 1u;
            #pragma unroll
            for (int k = 0; k < 4; k++) {
                mma_f16_ss(tmem, dA + 2*k,  dW + 2*k,  TCIDESC, en); en = 1u;
                mma_f16_ss(tmem, dA + 2*k,  dWl + 2*k, TCIDESC, 1u);
                mma_f16_ss(tmem, dAl + 2*k, dW + 2*k,  TCIDESC, 1u);
            }
            TC_COMMIT(mb0);
        }
        mbar_wait(mb0, (uint32_t)(i & 1));
    }
    TC_FENCE_AFTER();
    __syncthreads();

    // Epilogue: TMEM -> SMEM (pitch 129) -> coalesced global
    float* Cs = (float*)sm;
    #pragma unroll
    for (int cb = 0; cb < 4; cb++) {
        uint32_t regs[32];
        TC_LD32(regs, tmem + cb * 32);
        TC_WAIT_LD();
        const int row = wid * 32 + lid;
        #pragma unroll
        for (int c = 0; c < 32; c++)
            Cs[row * 129 + cb * 32 + c] = __uint_as_float(regs[c]);
    }
    TC_FENCE_BEFORE();
    __syncthreads();

    #pragma unroll
    for (int i2 = 0; i2 < 32; i2++) {
        int f = tid + i2 * 128;
        int r = f >> 5;
        int c4 = (f & 31) * 4;
        float4 o;
        o.x = Cs[r * 129 + c4 + 0];
        o.y = Cs[r * 129 + c4 + 1];
        o.z = Cs[r * 129 + c4 + 2];
        o.w = Cs[r * 129 + c4 + 3];
        size_t gi = (size_t)(bm + r) * GK + bn + c4;
        if (resid) {
            float4 rr = *(const float4*)(resid + gi);
            o.x += rr.x; o.y += rr.y; o.z += rr.z; o.w += rr.w;
        }
        *(float4*)(C + gi) = o;
    }

    __syncthreads();
    if (tid == 0) MBAR_INVAL(mb0);
    if (wid == 0) TC_DEALLOC(tmem, 128);

#else
    // ---------------- HMMA fallback: mma.sync bf16, cp.async 2-stage ----------------
    // SMEM stage (bf16 units, pitch 40): Ah@0, Al@5120, Bh@10240, Bl@15360.
    // Stage stride 20480 bf16 = 40960 B; 2 stages = 81920 B.
    extern __shared__ __nv_bfloat16 S[];
    const int tid  = threadIdx.x;
    const int lane = tid & 31;
    const int wid  = tid >> 5;
    const int bm = blockIdx.y * 128;
    const int bn = blockIdx.x * 128;
    const int wm = (wid & 1) * 64;
    const int wn = (wid >> 1) * 64;

    const __nv_bfloat16* gA  = Ah + (size_t)bm * GK;
    const __nv_bfloat16* gAl = Al + (size_t)bm * GK;
    const __nv_bfloat16* gB  = Wh + (size_t)bn * GK;
    const __nv_bfloat16* gBl = Wl + (size_t)bn * GK;

    const uint32_t sbase = smem_u32(S);

    // per-thread load coords (4 uint4 per matrix per stage)
    const int lr0 = tid >> 2;          // row 0..31 step... r = f>>2
    const int lu0 = tid & 3;

    float d[4][8][4];
    #pragma unroll
    for (int i = 0; i < 4; i++)
        #pragma unroll
        for (int j = 0; j < 8; j++)
            #pragma unroll
            for (int e = 0; e < 4; e++) d[i][j][e] = 0.f;

    // ldmatrix per-thread address components
    const uint32_t acb_row = (uint32_t)(lane & 15);   // row within 16
    const uint32_t acb_col = (uint32_t)((lane >> 4) * 8);

    // prologue: stage 0, k0 = 0
    {
        #pragma unroll
        for (int it = 0; it < 4; it++) {
            int f = tid + it * 128;
            int r = f >> 2;
            int u = f & 3;
            uint32_t so = sbase + (uint32_t)(r * 40 + u * 8) * 2;
            size_t go = (size_t)r * GK + u * 8;
            cpa16(so,          gA  + go);
            cpa16(so + 10240u, gAl + go);
            cpa16(so + 20480u, gB  + go);
            cpa16(so + 30720u, gBl + go);
        }
        CPA_COMMIT();
        CPA_WAIT0();
        __syncthreads();
    }

    for (int ic = 0; ic < 32; ic++) {
        const int st = ic & 1;
        if (ic + 1 < 32) {
            const int k0 = (ic + 1) * 32;
            const uint32_t sb2 = sbase + (uint32_t)((st ^ 1) * 40960);
            #pragma unroll
            for (int it = 0; it < 4; it++) {
                int f = tid + it * 128;
                int r = f >> 2;
                int u = f & 3;
                uint32_t so = sb2 + (uint32_t)(r * 40 + u * 8) * 2;
                size_t go = (size_t)r * GK + k0 + u * 8;
                cpa16(so,          gA  + go);
                cpa16(so + 10240u, gAl + go);
                cpa16(so + 20480u, gB  + go);
                cpa16(so + 30720u, gBl + go);
            }
        }
        CPA_COMMIT();

        const uint32_t sb = sbase + (uint32_t)(st * 40960);
        #pragma unroll
        for (int ks = 0; ks < 2; ks++) {
            const uint32_t cb = (uint32_t)(ks * 16) * 2 + acb_col * 2;

            uint32_t ah[4][4], bh[4][4];
            #pragma unroll
            for (int i = 0; i < 4; i++)
                ldm4(sb + (uint32_t)((wm + i * 16) + acb_row) * 80u + cb, ah[i]);
            #pragma unroll
            for (int nb = 0; nb < 4; nb++)
                ldm4(sb + 20480u + (uint32_t)((wn + nb * 16) + acb_row) * 80u + cb, bh[nb]);

            #pragma unroll
            for (int i = 0; i < 4; i++)
                #pragma unroll
                for (int nb = 0; nb < 4; nb++) {
                    mma16816(d[i][2*nb],     ah[i], bh[nb][0], bh[nb][2]);
                    mma16816(d[i][2*nb + 1], ah[i], bh[nb][1], bh[nb][3]);
                }

            {
                uint32_t bl[4][4];
                #pragma unroll
                for (int nb = 0; nb < 4; nb++)
                    ldm4(sb + 30720u + (uint32_t)((wn + nb * 16) + acb_row) * 80u + cb, bl[nb]);
                #pragma unroll
                for (int i = 0; i < 4; i++)
                    #pragma unroll
                    for (int nb = 0; nb < 4; nb++) {
                        mma16816(d[i][2*nb],     ah[i], bl[nb][0], bl[nb][2]);
                        mma16816(d[i][2*nb + 1], ah[i], bl[nb][1], bl[nb][3]);
                    }
            }
            {
                uint32_t al[4][4];
                #pragma unroll
                for (int i = 0; i < 4; i++)
                    ldm4(sb + 10240u + (uint32_t)((wm + i * 16) + acb_row) * 80u + cb, al[i]);
                #pragma unroll
                for (int i = 0; i < 4; i++)
                    #pragma unroll
                    for (int nb = 0; nb < 4; nb++) {
                        mma16816(d[i][2*nb],     al[i], bh[nb][0], bh[nb][2]);
                        mma16816(d[i][2*nb + 1], al[i], bh[nb][1], bh[nb][3]);
                    }
            }
        }
        CPA_WAIT0();
        __syncthreads();
    }

    // Epilogue: direct float2 stores (+resid)
    const int er = bm + wm + (lane >> 2);
    const int ec = bn + wn + (lane & 3) * 2;
    #pragma unroll
    for (int i = 0; i < 4; i++) {
        const int r1 = er + i * 16;
        #pragma unroll
        for (int jj = 0; jj < 8; jj++) {
            const int c = ec + jj * 8;
            float2 v0 = make_float2(d[i][jj][0], d[i][jj][1]);
            float2 v1 = make_float2(d[i][jj][2], d[i][jj][3]);
            size_t o0 = (size_t)r1 * GK + c;
            size_t o1 = (size_t)(r1 + 8) * GK + c;
            if (resid) {
                float2 q0 = *(const float2*)(resid + o0);
                float2 q1 = *(const float2*)(resid + o1);
                v0.x += q0.x; v0.y += q0.y;
                v1.x += q1.x; v1.y += q1.y;
            }
            *(float2*)(C + o0) = v0;
            *(float2*)(C + o1) = v1;
        }
    }
    (void)lr0; (void)lu0;
#endif
}

// ---------------------------------------------------------------------------
// fp32 -> bf16 hi/lo split (elementwise, float4)
// ---------------------------------------------------------------------------
__global__ __launch_bounds__(256) void conv_act(
    const float* __restrict__ X, __nv_bfloat16* __restrict__ H,
    __nv_bfloat16* __restrict__ L)
{
    int i = blockIdx.x * 256 + threadIdx.x;
    float4 v = ((const float4*)X)[i];
    float vv[4] = {v.x, v.y, v.z, v.w};
    __nv_bfloat16 h[4], l[4];
    #pragma unroll
    for (int j = 0; j < 4; j++) {
        h[j] = __float2bfloat16(vv[j]);
        l[j] = __float2bfloat16(vv[j] - __bfloat162float(h[j]));
    }
    uint64_t hp, lp;
    memcpy(&hp, h, 8); memcpy(&lp, l, 8);
    ((uint64_t*)H)[i] = hp;
    ((uint64_t*)L)[i] = lp;
}

// ---------------------------------------------------------------------------
// W [K][N] fp32 -> W^T hi/lo bf16 [N][K] (tiled transpose)
// ---------------------------------------------------------------------------
__global__ __launch_bounds__(256) void conv_wt(
    const float* __restrict__ W, __nv_bfloat16* __restrict__ TH,
    __nv_bfloat16* __restrict__ TL)
{
    __shared__ float t[32][33];
    const int bxn = blockIdx.x * 32;
    const int byk = blockIdx.y * 32;
    const int tx = threadIdx.x & 31;
    const int ty4 = (threadIdx.x >> 5) * 4;

    #pragma unroll
    for (int j = 0; j < 4; j++)
        t[ty4 + j][tx] = W[(size_t)(byk + ty4 + j) * Dd + bxn + tx];
    __syncthreads();

    #pragma unroll
    for (int j = 0; j < 4; j++) {
        float x = t[tx][ty4 + j];
        __nv_bfloat16 h = __float2bfloat16(x);
        __nv_bfloat16 l = __float2bfloat16(x - __bfloat162float(h));
        size_t o = (size_t)(bxn + ty4 + j) * Dd + byk + tx;
        TH[o] = h;
        TL[o] = l;
    }
}

// ---------------------------------------------------------------------------
// Causal flash attention, fp32, online softmax (round-1, proven).
// ---------------------------------------------------------------------------
#define ATTN_SMEM ((64*64 + 64*65 + 64*64) * 4)

__global__ __launch_bounds__(256) void attn_kernel(
    const float* __restrict__ Qp, const float* __restrict__ Kp,
    const float* __restrict__ Vp, float* __restrict__ Op)
{
    extern __shared__ float sm[];
    float* Qs  = sm;
    float* KPs = sm + 64 * 64;
    float* Vs  = KPs + 64 * 65;

    const int tid = threadIdx.x;
    const int tx = tid & 15;
    const int ty = tid >> 4;
    const int qt = blockIdx.x;
    const int h  = blockIdx.y;
    const int b  = blockIdx.z;
    const int q0 = qt * 64;

    const float* Qb = Qp + (size_t)b * Ss * Dd + h * HDd;
    const float* Kb = Kp + (size_t)b * Ss * Dd + h * HDd;
    const float* Vb = Vp + (size_t)b * Ss * Dd + h * HDd;

    #pragma unroll
    for (int it = 0; it < 4; it++) {
        int f = tid + (it << 8);
        int r = f >> 4;
        int c = (f & 15) << 2;
        *(float4*)(&Qs[r * 64 + c]) =
            *(const float4*)(Qb + (size_t)(q0 + r) * Dd + c);
    }

    float m_[4], l_[4], acc[4][4];
    #pragma unroll
    for (int i = 0; i < 4; i++) {
        m_[i] = -1e30f;
        l_[i] = 0.f;
        #pragma unroll
        for (int j = 0; j < 4; j++) acc[i][j] = 0.f;
    }

    for (int kt = 0; kt <= qt; kt++) {
        const int k0 = kt * 64;
        __syncthreads();

        #pragma unroll
        for (int it = 0; it < 4; it++) {
            int f = tid + (it << 8);
            int r = f >> 4;
            int c = (f & 15) << 2;
            float4 kv = *(const float4*)(Kb + (size_t)(k0 + r) * Dd + c);
            KPs[r * 65 + c + 0] = kv.x;
            KPs[r * 65 + c + 1] = kv.y;
            KPs[r * 65 + c + 2] = kv.z;
            KPs[r * 65 + c + 3] = kv.w;
            *(float4*)(&Vs[r * 64 + c]) =
                *(const float4*)(Vb + (size_t)(k0 + r) * Dd + c);
        }
        __syncthreads();

        float s[4][4];
        #pragma unroll
        for (int i = 0; i < 4; i++)
            #pragma unroll
            for (int j = 0; j < 4; j++) s[i][j] = 0.f;

        #pragma unroll 8
        for (int dk = 0; dk < 64; dk++) {
            float qa[4], kb[4];
            #pragma unroll
            for (int i = 0; i < 4; i++) qa[i] = Qs[(ty * 4 + i) * 64 + dk];
            #pragma unroll
            for (int j = 0; j < 4; j++) kb[j] = KPs[(tx * 4 + j) * 65 + dk];
            #pragma unroll
            for (int i = 0; i < 4; i++)
                #pragma unroll
                for (int j = 0; j < 4; j++)
                    s[i][j] += qa[i] * kb[j];
        }

        const bool diag = (kt == qt);
        #pragma unroll
        for (int i = 0; i < 4; i++)
            #pragma unroll
            for (int j = 0; j < 4; j++) {
                s[i][j] *= 0.125f;
                if (diag && (tx * 4 + j) > (ty * 4 + i)) s[i][j] = -1e30f;
            }

        float p[4][4];
        #pragma unroll
        for (int i = 0; i < 4; i++) {
            float mx = fmaxf(fmaxf(s[i][0], s[i][1]), fmaxf(s[i][2], s[i][3]));
            #pragma unroll
            for (int o = 8; o > 0; o >>= 1)
                mx = fmaxf(mx, __shfl_xor_sync(0xffffffffu, mx, o));
            float mn = fmaxf(m_[i], mx);
            float sum = 0.f;
            #pragma unroll
            for (int j = 0; j < 4; j++) {
                p[i][j] = __expf(s[i][j] - mn);
                sum += p[i][j];
            }
            #pragma unroll
            for (int o = 8; o > 0; o >>= 1)
                sum += __shfl_xor_sync(0xffffffffu, sum, o);
            float corr = __expf(m_[i] - mn);
            l_[i] = l_[i] * corr + sum;
            m_[i] = mn;
            #pragma unroll
            for (int j = 0; j < 4; j++) acc[i][j] *= corr;
        }

        __syncthreads();
        #pragma unroll
        for (int i = 0; i < 4; i++)
            #pragma unroll
            for (int j = 0; j < 4; j++)
                KPs[(ty * 4 + i) * 65 + tx * 4 + j] = p[i][j];
        __syncthreads();

        #pragma unroll 8
        for (int kk = 0; kk < 64; kk++) {
            float pa[4], vv[4];
            #pragma unroll
            for (int i = 0; i < 4; i++) pa[i] = KPs[(ty * 4 + i) * 65 + kk];
            #pragma unroll
            for (int j = 0; j < 4; j++) vv[j] = Vs[kk * 64 + tx * 4 + j];
            #pragma unroll
            for (int i = 0; i < 4; i++)
                #pragma unroll
                for (int j = 0; j < 4; j++)
                    acc[i][j] += pa[i] * vv[j];
        }
    }

    float* Ob = Op + (size_t)b * Ss * Dd + h * HDd;
    #pragma unroll
    for (int i = 0; i < 4; i++) {
        float inv = 1.0f / l_[i];
        float4 o;
        o.x = acc[i][0] * inv;
        o.y = acc[i][1] * inv;
        o.z = acc[i][2] * inv;
        o.w = acc[i][3] * inv;
        *(float4*)(Ob + (size_t)(q0 + ty * 4 + i) * Dd + tx * 4) = o;
    }
}

// ---------------------------------------------------------------------------
// LayerNorm over last dim (1024), one block (256 threads) per row.
// ---------------------------------------------------------------------------
__global__ __launch_bounds__(256) void ln_kernel(
    const float* __restrict__ X, const float* __restrict__ gamma,
    const float* __restrict__ beta, float* __restrict__ Y)
{
    const int row = blockIdx.x;
    const int t = threadIdx.x;
    const float4 v = ((const float4*)(X + (size_t)row * Dd))[t];

    float s  = v.x + v.y + v.z + v.w;
    float ss = v.x * v.x + v.y * v.y + v.z * v.z + v.w * v.w;
    #pragma unroll
    for (int o = 16; o > 0; o >>= 1) {
        s  += __shfl_xor_sync(0xffffffffu, s,  o);
        ss += __shfl_xor_sync(0xffffffffu, ss, o);
    }
    __shared__ float sh[8][2];
    if ((t & 31) == 0) { sh[t >> 5][0] = s; sh[t >> 5][1] = ss; }
    __syncthreads();
    float ts = 0.f, tss = 0.f;
    #pragma unroll
    for (int i = 0; i < 8; i++) { ts += sh[i][0]; tss += sh[i][1]; }

    const float mu  = ts * (1.0f / Dd);
    const float var = tss * (1.0f / Dd) - mu * mu;
    const float inv = rsqrtf(var + LN_EPS);

    const float4 gg = ((const float4*)gamma)[t];
    const float4 bb = ((const float4*)beta)[t];
    float4 y;
    y.x = (v.x - mu) * inv * gg.x + bb.x;
    y.y = (v.y - mu) * inv * gg.y + bb.y;
    y.z = (v.z - mu) * inv * gg.z + bb.z;
    y.w = (v.w - mu) * inv * gg.w + bb.w;
    ((float4*)(Y + (size_t)row * Dd))[t] = y;
}

// ---------------------------------------------------------------------------
// Launch. Inputs: q, k, v, wq, wk, wv, wo, gamma, beta, mask(unused: causal).
// ---------------------------------------------------------------------------
extern "C" void kernel_launch(void* const* d_in, const int* in_sizes, int n_in,
                              void* d_out, int out_size)
{
    const float* q     = (const float*)d_in[0];
    const float* k     = (const float*)d_in[1];
    const float* v     = (const float*)d_in[2];
    const float* wq    = (const float*)d_in[3];
    const float* wk    = (const float*)d_in[4];
    const float* wv    = (const float*)d_in[5];
    const float* wo    = (const float*)d_in[6];
    const float* gamma = (const float*)d_in[7];
    const float* beta  = (const float*)d_in[8];
    float* out = (float*)d_out;

    float *gq, *gk, *gv, *gatt, *gtmp;
    __nv_bfloat16 *gah, *gal, *gwh, *gwl;
    cudaGetSymbolAddress((void**)&gq,   g_q);
    cudaGetSymbolAddress((void**)&gk,   g_k);
    cudaGetSymbolAddress((void**)&gv,   g_v);
    cudaGetSymbolAddress((void**)&gatt, g_att);
    cudaGetSymbolAddress((void**)&gtmp, g_tmp);
    cudaGetSymbolAddress((void**)&gah,  g_ah);
    cudaGetSymbolAddress((void**)&gal,  g_al);
    cudaGetSymbolAddress((void**)&gwh,  g_wh);
    cudaGetSymbolAddress((void**)&gwl,  g_wl);

    cudaFuncSetAttribute(attn_kernel,
                         cudaFuncAttributeMaxDynamicSharedMemorySize, ATTN_SMEM);
    cudaFuncSetAttribute(gemm_tc,
                         cudaFuncAttributeMaxDynamicSharedMemorySize, GEMM_SMEM);

    const dim3 blk256(256);
    const dim3 blk128(128);
    const dim3 gconv(MS * Dd / 4 / 256);
    const dim3 gwt(Dd / 32, Dd / 32);
    const dim3 ggemm(Dd / 128, MS / 128);     // (8, 32)

    // Q projection
    conv_wt<<<gwt, blk256>>>(wq, gwh, gwl);
    conv_act<<<gconv, blk256>>>(q, gah, gal);
    gemm_tc<<<ggemm, blk128, GEMM_SMEM>>>(gah, gal, gwh, gwl, nullptr, gq);
    // K projection
    conv_wt<<<gwt, blk256>>>(wk, gwh, gwl);
    conv_act<<<gconv, blk256>>>(k, gah, gal);
    gemm_tc<<<ggemm, blk128, GEMM_SMEM>>>(gah, gal, gwh, gwl, nullptr, gk);
    // V projection
    conv_wt<<<gwt, blk256>>>(wv, gwh, gwl);
    conv_act<<<gconv, blk256>>>(v, gah, gal);
    gemm_tc<<<ggemm, blk128, GEMM_SMEM>>>(gah, gal, gwh, gwl, nullptr, gv);

    // attention
    dim3 ga(Ss / 64, Hh, Bb);
    attn_kernel<<<ga, blk256, ATTN_SMEM>>>(gq, gk, gv, gatt);

    // output projection + residual
    conv_wt<<<gwt, blk256>>>(wo, gwh, gwl);
    conv_act<<<gconv, blk256>>>(gatt, gah, gal);
    gemm_tc<<<ggemm, blk128, GEMM_SMEM>>>(gah, gal, gwh, gwl, q, gtmp);

    // LayerNorm
    ln_kernel<<<MS, blk256>>>(gtmp, gamma, beta, out);
}

// round 4
// speedup vs baseline: 2.9158x; 1.8260x over previous
#include <cuda_runtime.h>
#include <cuda_bf16.h>
#include <cstdint>

// Problem constants
#define Bb  2
#define Ss  2048
#define Dd  1024
#define Hh  16
#define HDd 64
#define MS  (Bb*Ss)          // 4096 rows
#define LN_EPS 1e-5f
#define GK 1024

#if defined(__CUDA_ARCH_FEAT_SM103_ALL)
#define USE_TC 1
#else
#define USE_TC 0
#endif

// ---------------------------------------------------------------------------
// Scratch (device globals)
// ---------------------------------------------------------------------------
__device__ float g_tmp[MS*Dd];          // pre-LN
__device__ __nv_bfloat16 g_ah[MS*Dd];   // input-activation hi (staging)
__device__ __nv_bfloat16 g_al[MS*Dd];
__device__ __nv_bfloat16 g_wh[Dd*Dd];   // weight^T hi [N][K]
__device__ __nv_bfloat16 g_wl[Dd*Dd];
__device__ __nv_bfloat16 g_qh[MS*Dd], g_ql[MS*Dd];
__device__ __nv_bfloat16 g_kh[MS*Dd], g_kl[MS*Dd];
__device__ __nv_bfloat16 g_vh[MS*Dd], g_vl[MS*Dd];
__device__ __nv_bfloat16 g_oh[MS*Dd], g_ol[MS*Dd];   // attention out split

// ---------------------------------------------------------------------------
// Base-arch helpers
// ---------------------------------------------------------------------------
__device__ __forceinline__ uint32_t smem_u32(const void* p) {
    uint32_t a;
    asm("{ .reg .u64 t; cvta.to.shared.u64 t, %1; cvt.u32.u64 %0, t; }"
        : "=r"(a) : "l"(p));
    return a;
}
__device__ __forceinline__ void cpa16(uint32_t s, const void* g) {
    asm volatile("cp.async.cg.shared.global [%0], [%1], 16;" :: "r"(s), "l"(g));
}
#define CPA_COMMIT() asm volatile("cp.async.commit_group;" ::: "memory")
#define CPA_WAIT0()  asm volatile("cp.async.wait_group 0;" ::: "memory")
#define CPA_WAIT1()  asm volatile("cp.async.wait_group 1;" ::: "memory")

__device__ __forceinline__ void ldm4(uint32_t a, uint32_t r[4]) {
    asm volatile("ldmatrix.sync.aligned.m8n8.x4.shared.b16 {%0,%1,%2,%3}, [%4];"
                 : "=r"(r[0]), "=r"(r[1]), "=r"(r[2]), "=r"(r[3]) : "r"(a));
}
__device__ __forceinline__ void ldm4t(uint32_t a, uint32_t r[4]) {
    asm volatile("ldmatrix.sync.aligned.m8n8.x4.trans.shared.b16 {%0,%1,%2,%3}, [%4];"
                 : "=r"(r[0]), "=r"(r[1]), "=r"(r[2]), "=r"(r[3]) : "r"(a));
}
__device__ __forceinline__ void mma16816(float d[4], const uint32_t a[4],
                                         uint32_t b0, uint32_t b1) {
    asm volatile(
        "mma.sync.aligned.m16n8k16.row.col.f32.bf16.bf16.f32 "
        "{%0,%1,%2,%3}, {%4,%5,%6,%7}, {%8,%9}, {%0,%1,%2,%3};"
        : "+f"(d[0]), "+f"(d[1]), "+f"(d[2]), "+f"(d[3])
        : "r"(a[0]), "r"(a[1]), "r"(a[2]), "r"(a[3]), "r"(b0), "r"(b1));
}
// split fp32 pair -> bf16x2 (hi) + bf16x2 (lo)
__device__ __forceinline__ void pack_split(float x, float y,
                                           uint32_t& hi, uint32_t& lo) {
    __nv_bfloat16 hx = __float2bfloat16(x), hy = __float2bfloat16(y);
    __nv_bfloat16 lx = __float2bfloat16(x - __bfloat162float(hx));
    __nv_bfloat16 ly = __float2bfloat16(y - __bfloat162float(hy));
    hi = (uint32_t)__bfloat16_as_ushort(hx) | ((uint32_t)__bfloat16_as_ushort(hy) << 16);
    lo = (uint32_t)__bfloat16_as_ushort(lx) | ((uint32_t)__bfloat16_as_ushort(ly) << 16);
}

#define GEMM_SMEM 81920

#if USE_TC
// ---------------------------------------------------------------------------
// tcgen05 helpers ('a' pass only — currently inert, base pass is live)
// ---------------------------------------------------------------------------
__device__ __forceinline__ uint32_t elect1() {
    uint32_t p;
    asm volatile("{ .reg .pred p; elect.sync _|p, 0xFFFFFFFF; selp.b32 %0,1,0,p; }"
                 : "=r"(p));
    return p;
}
#define MBAR_INIT(a, c) \
    asm volatile("mbarrier.init.shared.b64 [%0], %1;" :: "r"(a), "r"(c) : "memory")
#define MBAR_INVAL(a) \
    asm volatile("mbarrier.inval.shared.b64 [%0];" :: "r"(a) : "memory")
__device__ __forceinline__ void mbar_wait(uint32_t addr, uint32_t parity) {
    asm volatile(
        "{\n\t.reg .pred P;\n\t"
        "WL_%=:\n\t"
        "mbarrier.try_wait.parity.acquire.cta.shared::cta.b64 P, [%0], %1, 0x989680;\n\t"
        "@P bra WD_%=;\n\t"
        "bra WL_%=;\n\t"
        "WD_%=:\n\t}"
        :: "r"(addr), "r"(parity) : "memory");
}
#define TC_ALLOC(sa, n) \
    asm volatile("tcgen05.alloc.cta_group::1.sync.aligned.shared::cta.b32 [%0], %1;" \
                 :: "r"(sa), "r"(n) : "memory")
#define TC_RELINQ() \
    asm volatile("tcgen05.relinquish_alloc_permit.cta_group::1.sync.aligned;")
#define TC_DEALLOC(t, n) \
    asm volatile("tcgen05.dealloc.cta_group::1.sync.aligned.b32 %0, %1;" :: "r"(t), "r"(n))
#define TC_COMMIT(mb) \
    asm volatile("tcgen05.commit.cta_group::1.mbarrier::arrive::one.shared::cluster.b64 [%0];" \
                 :: "r"(mb) : "memory")
#define TC_FENCE_AFTER()  asm volatile("tcgen05.fence::after_thread_sync;" ::: "memory")
#define TC_FENCE_BEFORE() asm volatile("tcgen05.fence::before_thread_sync;" ::: "memory")
#define TC_WAIT_LD()      asm volatile("tcgen05.wait::ld.sync.aligned;" ::: "memory")
#define FENCE_ASYNC()     asm volatile("fence.proxy.async.shared::cta;" ::: "memory")
#define TC_LD32(r, ta) \
    asm volatile( \
        "tcgen05.ld.sync.aligned.32x32b.x32.b32 " \
        "{%0, %1, %2, %3, %4, %5, %6, %7, " \
        " %8, %9, %10, %11, %12, %13, %14, %15, " \
        " %16, %17, %18, %19, %20, %21, %22, %23, " \
        " %24, %25, %26, %27, %28, %29, %30, %31}, [%32];" \
        : "=r"((r)[0]),  "=r"((r)[1]),  "=r"((r)[2]),  "=r"((r)[3]), \
          "=r"((r)[4]),  "=r"((r)[5]),  "=r"((r)[6]),  "=r"((r)[7]), \
          "=r"((r)[8]),  "=r"((r)[9]),  "=r"((r)[10]), "=r"((r)[11]), \
          "=r"((r)[12]), "=r"((r)[13]), "=r"((r)[14]), "=r"((r)[15]), \
          "=r"((r)[16]), "=r"((r)[17]), "=r"((r)[18]), "=r"((r)[19]), \
          "=r"((r)[20]), "=r"((r)[21]), "=r"((r)[22]), "=r"((r)[23]), \
          "=r"((r)[24]), "=r"((r)[25]), "=r"((r)[26]), "=r"((r)[27]), \
          "=r"((r)[28]), "=r"((r)[29]), "=r"((r)[30]), "=r"((r)[31]) \
        : "r"(ta))
__device__ __forceinline__ uint64_t mk_desc(uint32_t sa) {
    return ((uint64_t)2 << 61) | ((uint64_t)1 << 46) | ((uint64_t)64 << 32)
         | ((uint64_t)1 << 16) | (uint64_t)((sa >> 4) & 0x3FFF);
}
__device__ __forceinline__ void mma_f16_ss(uint32_t d, uint64_t a, uint64_t b,
                                           uint32_t idesc, uint32_t en) {
    asm volatile(
        "{\n\t.reg .pred p;\n\t"
        "setp.ne.u32 p, %4, 0;\n\t"
        "tcgen05.mma.cta_group::1.kind::f16 [%0], %1, %2, %3, {%5, %5, %5, %5}, p;\n\t"
        "}"
        :: "r"(d), "l"(a), "l"(b), "r"(idesc), "r"(en), "r"(0u)
        : "memory");
}
#define TCIDESC ((1u << 4) | (1u << 7) | (1u << 10) | ((128u / 8) << 17) | ((128u / 16) << 24))
#define TCTILE_B (128 * 64 * 2)
__device__ __forceinline__ void tc_load_tile(char* dst, const __nv_bfloat16* src, int tid) {
    #pragma unroll
    for (int it = 0; it < 8; it++) {
        int f = tid + it * 128;
        int r = f >> 3;
        int u = f & 7;
        uint4 v = ((const uint4*)(src + (size_t)r * GK))[u];
        uint32_t off = (uint32_t)(r * 128 + u * 16);
        off ^= (off >> 3) & 0x70;
        *(uint4*)(dst + off) = v;
    }
}
#endif // USE_TC

// ---------------------------------------------------------------------------
// Split-bf16 GEMM: out[4096,1024] = A @ W (+resid).
// If OH != null: write bf16 hi/lo split to OH/OL; else fp32 (+resid) to C.
// ---------------------------------------------------------------------------
__global__ __launch_bounds__(128) __cluster_dims__(1, 1, 1)
void gemm_tc(const __nv_bfloat16* __restrict__ Ah, const __nv_bfloat16* __restrict__ Al,
             const __nv_bfloat16* __restrict__ Wh, const __nv_bfloat16* __restrict__ Wl,
             const float* __restrict__ resid, float* __restrict__ C,
             __nv_bfloat16* __restrict__ OH, __nv_bfloat16* __restrict__ OL)
{
#if USE_TC
    extern __shared__ char smraw[];
    __shared__ uint32_t s_tptr[1];
    __shared__ __align__(8) uint64_t s_mbar[1];

    const int tid = threadIdx.x;
    const int wid = tid >> 5;
    const int lid = tid & 31;
    const int bm = blockIdx.y * 128;
    const int bn = blockIdx.x * 128;

    uint32_t smb0 = smem_u32(smraw);
    char* sm = smraw + (((smb0 + 1023u) & ~1023u) - smb0);
    uint32_t mb0 = smem_u32(&s_mbar[0]);

    if (wid == 0) { TC_ALLOC(smem_u32(s_tptr), 128); TC_RELINQ(); }
    if (tid == 0) MBAR_INIT(mb0, 1);
    __syncthreads();
    const uint32_t tmem = s_tptr[0];

    const __nv_bfloat16* srcA  = Ah + (size_t)bm * GK;
    const __nv_bfloat16* srcAl = Al + (size_t)bm * GK;
    const __nv_bfloat16* srcW  = Wh + (size_t)bn * GK;
    const __nv_bfloat16* srcWl = Wl + (size_t)bn * GK;

    for (int i = 0; i < 16; i++) {
        const int k0 = i * 64;
        tc_load_tile(sm,              srcA  + k0, tid);
        tc_load_tile(sm + TCTILE_B,   srcAl + k0, tid);
        tc_load_tile(sm + 2*TCTILE_B, srcW  + k0, tid);
        tc_load_tile(sm + 3*TCTILE_B, srcWl + k0, tid);
        FENCE_ASYNC();
        __syncthreads();
        if (wid == 0 && elect1()) {
            uint64_t dA  = mk_desc(smem_u32(sm));
            uint64_t dAl = mk_desc(smem_u32(sm + TCTILE_B));
            uint64_t dW  = mk_desc(smem_u32(sm + 2*TCTILE_B));
            uint64_t dWl = mk_desc(smem_u32(sm + 3*TCTILE_B));
            uint32_t en = (i == 0) ? 0u : 1u;
            #pragma unroll
            for (int k = 0; k < 4; k++) {
                mma_f16_ss(tmem, dA + 2*k,  dW + 2*k,  TCIDESC, en); en = 1u;
                mma_f16_ss(tmem, dA + 2*k,  dWl + 2*k, TCIDESC, 1u);
                mma_f16_ss(tmem, dAl + 2*k, dW + 2*k,  TCIDESC, 1u);
            }
            TC_COMMIT(mb0);
        }
        mbar_wait(mb0, (uint32_t)(i & 1));
    }
    TC_FENCE_AFTER();
    __syncthreads();

    float* Cs = (float*)sm;
    #pragma unroll
    for (int cb = 0; cb < 4; cb++) {
        uint32_t regs[32];
        TC_LD32(regs, tmem + cb * 32);
        TC_WAIT_LD();
        const int row = wid * 32 + lid;
        #pragma unroll
        for (int c = 0; c < 32; c++)
            Cs[row * 129 + cb * 32 + c] = __uint_as_float(regs[c]);
    }
    TC_FENCE_BEFORE();
    __syncthreads();

    #pragma unroll
    for (int i2 = 0; i2 < 32; i2++) {
        int f = tid + i2 * 128;
        int r = f >> 5;
        int c4 = (f & 31) * 4;
        float4 o;
        o.x = Cs[r * 129 + c4 + 0];
        o.y = Cs[r * 129 + c4 + 1];
        o.z = Cs[r * 129 + c4 + 2];
        o.w = Cs[r * 129 + c4 + 3];
        size_t gi = (size_t)(bm + r) * GK + bn + c4;
        if (OH) {
            uint32_t h0, l0, h1, l1;
            pack_split(o.x, o.y, h0, l0);
            pack_split(o.z, o.w, h1, l1);
            *(uint32_t*)(OH + gi) = h0; *(uint32_t*)(OH + gi + 2) = h1;
            *(uint32_t*)(OL + gi) = l0; *(uint32_t*)(OL + gi + 2) = l1;
        } else {
            if (resid) {
                float4 rr = *(const float4*)(resid + gi);
                o.x += rr.x; o.y += rr.y; o.z += rr.z; o.w += rr.w;
            }
            *(float4*)(C + gi) = o;
        }
    }
    __syncthreads();
    if (tid == 0) MBAR_INVAL(mb0);
    if (wid == 0) TC_DEALLOC(tmem, 128);

#else
    // HMMA fallback (live path)
    extern __shared__ __nv_bfloat16 S[];
    const int tid  = threadIdx.x;
    const int lane = tid & 31;
    const int wid  = tid >> 5;
    const int bm = blockIdx.y * 128;
    const int bn = blockIdx.x * 128;
    const int wm = (wid & 1) * 64;
    const int wn = (wid >> 1) * 64;

    const __nv_bfloat16* gA  = Ah + (size_t)bm * GK;
    const __nv_bfloat16* gAl = Al + (size_t)bm * GK;
    const __nv_bfloat16* gB  = Wh + (size_t)bn * GK;
    const __nv_bfloat16* gBl = Wl + (size_t)bn * GK;

    const uint32_t sbase = smem_u32(S);

    float d[4][8][4];
    #pragma unroll
    for (int i = 0; i < 4; i++)
        #pragma unroll
        for (int j = 0; j < 8; j++)
            #pragma unroll
            for (int e = 0; e < 4; e++) d[i][j][e] = 0.f;

    const uint32_t acb_row = (uint32_t)(lane & 15);
    const uint32_t acb_col = (uint32_t)((lane >> 4) * 8);

    {
        #pragma unroll
        for (int it = 0; it < 4; it++) {
            int f = tid + it * 128;
            int r = f >> 2;
            int u = f & 3;
            uint32_t so = sbase + (uint32_t)(r * 40 + u * 8) * 2;
            size_t go = (size_t)r * GK + u * 8;
            cpa16(so,          gA  + go);
            cpa16(so + 10240u, gAl + go);
            cpa16(so + 20480u, gB  + go);
            cpa16(so + 30720u, gBl + go);
        }
        CPA_COMMIT();
        CPA_WAIT0();
        __syncthreads();
    }

    for (int ic = 0; ic < 32; ic++) {
        const int st = ic & 1;
        if (ic + 1 < 32) {
            const int k0 = (ic + 1) * 32;
            const uint32_t sb2 = sbase + (uint32_t)((st ^ 1) * 40960);
            #pragma unroll
            for (int it = 0; it < 4; it++) {
                int f = tid + it * 128;
                int r = f >> 2;
                int u = f & 3;
                uint32_t so = sb2 + (uint32_t)(r * 40 + u * 8) * 2;
                size_t go = (size_t)r * GK + k0 + u * 8;
                cpa16(so,          gA  + go);
                cpa16(so + 10240u, gAl + go);
                cpa16(so + 20480u, gB  + go);
                cpa16(so + 30720u, gBl + go);
            }
        }
        CPA_COMMIT();

        const uint32_t sb = sbase + (uint32_t)(st * 40960);
        #pragma unroll
        for (int ks = 0; ks < 2; ks++) {
            const uint32_t cb = (uint32_t)(ks * 16) * 2 + acb_col * 2;

            uint32_t ah[4][4], bh[4][4];
            #pragma unroll
            for (int i = 0; i < 4; i++)
                ldm4(sb + (uint32_t)((wm + i * 16) + acb_row) * 80u + cb, ah[i]);
            #pragma unroll
            for (int nb = 0; nb < 4; nb++)
                ldm4(sb + 20480u + (uint32_t)((wn + nb * 16) + acb_row) * 80u + cb, bh[nb]);

            #pragma unroll
            for (int i = 0; i < 4; i++)
                #pragma unroll
                for (int nb = 0; nb < 4; nb++) {
                    mma16816(d[i][2*nb],     ah[i], bh[nb][0], bh[nb][2]);
                    mma16816(d[i][2*nb + 1], ah[i], bh[nb][1], bh[nb][3]);
                }
            {
                uint32_t bl[4][4];
                #pragma unroll
                for (int nb = 0; nb < 4; nb++)
                    ldm4(sb + 30720u + (uint32_t)((wn + nb * 16) + acb_row) * 80u + cb, bl[nb]);
                #pragma unroll
                for (int i = 0; i < 4; i++)
                    #pragma unroll
                    for (int nb = 0; nb < 4; nb++) {
                        mma16816(d[i][2*nb],     ah[i], bl[nb][0], bl[nb][2]);
                        mma16816(d[i][2*nb + 1], ah[i], bl[nb][1], bl[nb][3]);
                    }
            }
            {
                uint32_t al[4][4];
                #pragma unroll
                for (int i = 0; i < 4; i++)
                    ldm4(sb + 10240u + (uint32_t)((wm + i * 16) + acb_row) * 80u + cb, al[i]);
                #pragma unroll
                for (int i = 0; i < 4; i++)
                    #pragma unroll
                    for (int nb = 0; nb < 4; nb++) {
                        mma16816(d[i][2*nb],     al[i], bh[nb][0], bh[nb][2]);
                        mma16816(d[i][2*nb + 1], al[i], bh[nb][1], bh[nb][3]);
                    }
            }
        }
        CPA_WAIT0();
        __syncthreads();
    }

    const int er = bm + wm + (lane >> 2);
    const int ec = bn + wn + (lane & 3) * 2;
    #pragma unroll
    for (int i = 0; i < 4; i++) {
        const int r1 = er + i * 16;
        #pragma unroll
        for (int jj = 0; jj < 8; jj++) {
            const int c = ec + jj * 8;
            size_t o0 = (size_t)r1 * GK + c;
            size_t o1 = (size_t)(r1 + 8) * GK + c;
            if (OH) {
                uint32_t hu, lu;
                pack_split(d[i][jj][0], d[i][jj][1], hu, lu);
                *(uint32_t*)(OH + o0) = hu;
                *(uint32_t*)(OL + o0) = lu;
                pack_split(d[i][jj][2], d[i][jj][3], hu, lu);
                *(uint32_t*)(OH + o1) = hu;
                *(uint32_t*)(OL + o1) = lu;
            } else {
                float2 v0 = make_float2(d[i][jj][0], d[i][jj][1]);
                float2 v1 = make_float2(d[i][jj][2], d[i][jj][3]);
                if (resid) {
                    float2 q0 = *(const float2*)(resid + o0);
                    float2 q1 = *(const float2*)(resid + o1);
                    v0.x += q0.x; v0.y += q0.y;
                    v1.x += q1.x; v1.y += q1.y;
                }
                *(float2*)(C + o0) = v0;
                *(float2*)(C + o1) = v1;
            }
        }
    }
#endif
}

// ---------------------------------------------------------------------------
// fp32 -> bf16 hi/lo split (inputs only)
// ---------------------------------------------------------------------------
__global__ __launch_bounds__(256) void conv_act(
    const float* __restrict__ X, __nv_bfloat16* __restrict__ H,
    __nv_bfloat16* __restrict__ L)
{
    int i = blockIdx.x * 256 + threadIdx.x;
    float4 v = ((const float4*)X)[i];
    float vv[4] = {v.x, v.y, v.z, v.w};
    __nv_bfloat16 h[4], l[4];
    #pragma unroll
    for (int j = 0; j < 4; j++) {
        h[j] = __float2bfloat16(vv[j]);
        l[j] = __float2bfloat16(vv[j] - __bfloat162float(h[j]));
    }
    uint64_t hp, lp;
    memcpy(&hp, h, 8); memcpy(&lp, l, 8);
    ((uint64_t*)H)[i] = hp;
    ((uint64_t*)L)[i] = lp;
}

// ---------------------------------------------------------------------------
// W [K][N] fp32 -> W^T hi/lo bf16 [N][K]
// ---------------------------------------------------------------------------
__global__ __launch_bounds__(256) void conv_wt(
    const float* __restrict__ W, __nv_bfloat16* __restrict__ TH,
    __nv_bfloat16* __restrict__ TL)
{
    __shared__ float t[32][33];
    const int bxn = blockIdx.x * 32;
    const int byk = blockIdx.y * 32;
    const int tx = threadIdx.x & 31;
    const int ty4 = (threadIdx.x >> 5) * 4;

    #pragma unroll
    for (int j = 0; j < 4; j++)
        t[ty4 + j][tx] = W[(size_t)(byk + ty4 + j) * Dd + bxn + tx];
    __syncthreads();

    #pragma unroll
    for (int j = 0; j < 4; j++) {
        float x = t[tx][ty4 + j];
        __nv_bfloat16 h = __float2bfloat16(x);
        __nv_bfloat16 l = __float2bfloat16(x - __bfloat162float(h));
        size_t o = (size_t)(bxn + ty4 + j) * Dd + byk + tx;
        TH[o] = h;
        TL[o] = l;
    }
}

// ---------------------------------------------------------------------------
// HMMA flash attention (causal). CTA = 128 q rows x one (b,h); 8 warps.
// K/V tiles of 64 keys, cp.async double-buffered. Split-bf16 on Q,K,P,V.
// ---------------------------------------------------------------------------
#define AT_PITCH  72
#define AT_ROWB   144
#define AT_TILE_B (64 * AT_ROWB)      // 9216
#define AT_STAGE_B (4 * AT_TILE_B)    // 36864
#define ATTN2_SMEM (2 * AT_STAGE_B)   // 73728
#define CS 0.18033688011112042f      // log2(e)/8

__global__ __launch_bounds__(256) void attn_tc(
    const __nv_bfloat16* __restrict__ Qh, const __nv_bfloat16* __restrict__ Ql,
    const __nv_bfloat16* __restrict__ Kh, const __nv_bfloat16* __restrict__ Kl,
    const __nv_bfloat16* __restrict__ Vh, const __nv_bfloat16* __restrict__ Vl,
    __nv_bfloat16* __restrict__ Oh, __nv_bfloat16* __restrict__ Ol)
{
    extern __shared__ char smc[];
    const int tid = threadIdx.x;
    const int lane = tid & 31;
    const int w = tid >> 5;
    const int bx = blockIdx.x, h = blockIdx.y, b = blockIdx.z;
    const int q0 = bx * 128;
    const uint32_t sb = smem_u32(smc);
    const size_t headoff = (size_t)b * Ss * Dd + (size_t)h * HDd;

    // ---- Q tiles -> SMEM (hi @0, lo @18432), then frags -> registers
    {
        const __nv_bfloat16* gq  = Qh + headoff + (size_t)q0 * Dd;
        const __nv_bfloat16* gql = Ql + headoff + (size_t)q0 * Dd;
        #pragma unroll
        for (int it = 0; it < 4; it++) {
            int f = tid + it * 256;          // 0..1023
            int r = f >> 3, ch = f & 7;
            uint32_t so = sb + (uint32_t)(r * AT_ROWB + ch * 16);
            size_t go = (size_t)r * Dd + ch * 8;
            cpa16(so, gq + go);
            cpa16(so + 18432u, gql + go);
        }
        CPA_COMMIT();
        CPA_WAIT0();
    }
    __syncthreads();

    uint32_t qh[4][4], ql[4][4];
    {
        uint32_t base = sb + (uint32_t)((16 * w + (lane & 15)) * AT_ROWB
                                        + (lane >> 4) * 16);
        #pragma unroll
        for (int c = 0; c < 4; c++) {
            ldm4(base + (uint32_t)(c * 32), qh[c]);
            ldm4(base + 18432u + (uint32_t)(c * 32), ql[c]);
        }
    }
    __syncthreads();   // done with Q smem; K/V loads may overwrite

    float oacc[8][4];
    #pragma unroll
    for (int i = 0; i < 8; i++)
        #pragma unroll
        for (int e = 0; e < 4; e++) oacc[i][e] = 0.f;
    float m0 = -1e30f, m1 = -1e30f, l0 = 0.f, l1 = 0.f;
    const int r0g = q0 + 16 * w + (lane >> 2);
    const int r1g = r0g + 8;

    const int nkt = 2 * bx + 2;
    const __nv_bfloat16 *gkh = Kh + headoff, *gkl = Kl + headoff;
    const __nv_bfloat16 *gvh = Vh + headoff, *gvl = Vl + headoff;

    // prologue: tile 0 -> stage 0
    #pragma unroll
    for (int it = 0; it < 2; it++) {
        int f = tid + it * 256;              // 0..511
        int r = f >> 3, ch = f & 7;
        uint32_t so = sb + (uint32_t)(r * AT_ROWB + ch * 16);
        size_t go = (size_t)r * Dd + ch * 8;
        cpa16(so,                  gkh + go);
        cpa16(so + AT_TILE_B,      gkl + go);
        cpa16(so + 2 * AT_TILE_B,  gvh + go);
        cpa16(so + 3 * AT_TILE_B,  gvl + go);
    }
    CPA_COMMIT();

    for (int kt = 0; kt < nkt; kt++) {
        __syncthreads();     // all warps finished reading previous stage
        if (kt + 1 < nkt) {
            const uint32_t st2 = sb + (uint32_t)(((kt + 1) & 1) * AT_STAGE_B);
            const size_t kb = (size_t)(kt + 1) * 64 * Dd;
            #pragma unroll
            for (int it = 0; it < 2; it++) {
                int f = tid + it * 256;
                int r = f >> 3, ch = f & 7;
                uint32_t so = st2 + (uint32_t)(r * AT_ROWB + ch * 16);
                size_t go = kb + (size_t)r * Dd + ch * 8;
                cpa16(so,                 gkh + go);
                cpa16(so + AT_TILE_B,     gkl + go);
                cpa16(so + 2 * AT_TILE_B, gvh + go);
                cpa16(so + 3 * AT_TILE_B, gvl + go);
            }
            CPA_COMMIT();
            CPA_WAIT1();
        } else {
            CPA_WAIT0();
        }
        __syncthreads();     // current stage visible to all

        const int k0 = kt * 64;
        const bool active = (k0 <= q0 + 16 * w + 15);   // warp-uniform
        if (active) {
            const uint32_t stg = sb + (uint32_t)((kt & 1) * AT_STAGE_B);
            // ---- S = Qh*Kh + Qh*Kl + Ql*Kh
            float sacc[8][4];
            #pragma unroll
            for (int i = 0; i < 8; i++)
                #pragma unroll
                for (int e = 0; e < 4; e++) sacc[i][e] = 0.f;

            const uint32_t lb = stg + (uint32_t)((lane & 15) * AT_ROWB
                                                 + (lane >> 4) * 16);
            #pragma unroll
            for (int c = 0; c < 4; c++) {
                #pragma unroll
                for (int g = 0; g < 4; g++) {
                    uint32_t kh4[4], kl4[4];
                    uint32_t a = lb + (uint32_t)(g * 16 * AT_ROWB + c * 32);
                    ldm4(a, kh4);
                    ldm4(a + AT_TILE_B, kl4);
                    mma16816(sacc[2*g],   qh[c], kh4[0], kh4[2]);
                    mma16816(sacc[2*g+1], qh[c], kh4[1], kh4[3]);
                    mma16816(sacc[2*g],   qh[c], kl4[0], kl4[2]);
                    mma16816(sacc[2*g+1], qh[c], kl4[1], kl4[3]);
                    mma16816(sacc[2*g],   ql[c], kh4[0], kh4[2]);
                    mma16816(sacc[2*g+1], ql[c], kh4[1], kh4[3]);
                }
            }

            // ---- causal mask
            if (k0 + 63 > q0 + 16 * w) {
                #pragma unroll
                for (int nb = 0; nb < 8; nb++) {
                    int col = k0 + nb * 8 + (lane & 3) * 2;
                    if (col     > r0g) sacc[nb][0] = -1e30f;
                    if (col + 1 > r0g) sacc[nb][1] = -1e30f;
                    if (col     > r1g) sacc[nb][2] = -1e30f;
                    if (col + 1 > r1g) sacc[nb][3] = -1e30f;
                }
            }

            // ---- online softmax (rows r0g / r1g; 4 lanes per row)
            float mx0 = -1e30f, mx1 = -1e30f;
            #pragma unroll
            for (int nb = 0; nb < 8; nb++) {
                mx0 = fmaxf(mx0, fmaxf(sacc[nb][0], sacc[nb][1]));
                mx1 = fmaxf(mx1, fmaxf(sacc[nb][2], sacc[nb][3]));
            }
            mx0 = fmaxf(mx0, __shfl_xor_sync(0xffffffffu, mx0, 1));
            mx0 = fmaxf(mx0, __shfl_xor_sync(0xffffffffu, mx0, 2));
            mx1 = fmaxf(mx1, __shfl_xor_sync(0xffffffffu, mx1, 1));
            mx1 = fmaxf(mx1, __shfl_xor_sync(0xffffffffu, mx1, 2));
            const float nm0 = fmaxf(m0, mx0), nm1 = fmaxf(m1, mx1);
            const float a0 = exp2f((m0 - nm0) * CS);
            const float a1 = exp2f((m1 - nm1) * CS);
            m0 = nm0; m1 = nm1;
            const float c0 = nm0 * CS, c1 = nm1 * CS;
            float s0 = 0.f, s1 = 0.f;
            #pragma unroll
            for (int nb = 0; nb < 8; nb++) {
                float p0 = exp2f(fmaf(sacc[nb][0], CS, -c0));
                float p1 = exp2f(fmaf(sacc[nb][1], CS, -c0));
                float p2 = exp2f(fmaf(sacc[nb][2], CS, -c1));
                float p3 = exp2f(fmaf(sacc[nb][3], CS, -c1));
                sacc[nb][0] = p0; sacc[nb][1] = p1;
                sacc[nb][2] = p2; sacc[nb][3] = p3;
                s0 += p0 + p1;
                s1 += p2 + p3;
            }
            s0 += __shfl_xor_sync(0xffffffffu, s0, 1);
            s0 += __shfl_xor_sync(0xffffffffu, s0, 2);
            s1 += __shfl_xor_sync(0xffffffffu, s1, 1);
            s1 += __shfl_xor_sync(0xffffffffu, s1, 2);
            l0 = l0 * a0 + s0;
            l1 = l1 * a1 + s1;
            #pragma unroll
            for (int i = 0; i < 8; i++) {
                oacc[i][0] *= a0; oacc[i][1] *= a0;
                oacc[i][2] *= a1; oacc[i][3] *= a1;
            }

            // ---- O += Ph*Vh + Ph*Vl + Pl*Vh (P from registers)
            #pragma unroll
            for (int j = 0; j < 4; j++) {
                uint32_t pa[4], pl[4];
                pack_split(sacc[2*j][0],   sacc[2*j][1],   pa[0], pl[0]);
                pack_split(sacc[2*j][2],   sacc[2*j][3],   pa[1], pl[1]);
                pack_split(sacc[2*j+1][0], sacc[2*j+1][1], pa[2], pl[2]);
                pack_split(sacc[2*j+1][2], sacc[2*j+1][3], pa[3], pl[3]);
                const uint32_t vb = stg + 2 * AT_TILE_B
                    + (uint32_t)((16 * j + (lane & 15)) * AT_ROWB + (lane >> 4) * 16);
                #pragma unroll
                for (int dp = 0; dp < 4; dp++) {
                    uint32_t vh4[4], vl4[4];
                    ldm4t(vb + (uint32_t)(dp * 32), vh4);
                    ldm4t(vb + AT_TILE_B + (uint32_t)(dp * 32), vl4);
                    mma16816(oacc[2*dp],   pa, vh4[0], vh4[1]);
                    mma16816(oacc[2*dp+1], pa, vh4[2], vh4[3]);
                    mma16816(oacc[2*dp],   pa, vl4[0], vl4[1]);
                    mma16816(oacc[2*dp+1], pa, vl4[2], vl4[3]);
                    mma16816(oacc[2*dp],   pl, vh4[0], vh4[1]);
                    mma16816(oacc[2*dp+1], pl, vh4[2], vh4[3]);
                }
            }
        }
    }

    // ---- epilogue: O/l -> bf16 hi/lo global
    const float i0 = 1.f / l0, i1 = 1.f / l1;
    const size_t ro0 = (size_t)b * Ss * Dd + (size_t)r0g * Dd + (size_t)h * HDd;
    const size_t ro1 = ro0 + 8 * Dd;
    #pragma unroll
    for (int nb = 0; nb < 8; nb++) {
        const int dcol = nb * 8 + (lane & 3) * 2;
        uint32_t hu, lu;
        pack_split(oacc[nb][0] * i0, oacc[nb][1] * i0, hu, lu);
        *(uint32_t*)(Oh + ro0 + dcol) = hu;
        *(uint32_t*)(Ol + ro0 + dcol) = lu;
        pack_split(oacc[nb][2] * i1, oacc[nb][3] * i1, hu, lu);
        *(uint32_t*)(Oh + ro1 + dcol) = hu;
        *(uint32_t*)(Ol + ro1 + dcol) = lu;
    }
}

// ---------------------------------------------------------------------------
// LayerNorm over last dim (1024)
// ---------------------------------------------------------------------------
__global__ __launch_bounds__(256) void ln_kernel(
    const float* __restrict__ X, const float* __restrict__ gamma,
    const float* __restrict__ beta, float* __restrict__ Y)
{
    const int row = blockIdx.x;
    const int t = threadIdx.x;
    const float4 v = ((const float4*)(X + (size_t)row * Dd))[t];

    float s  = v.x + v.y + v.z + v.w;
    float ss = v.x * v.x + v.y * v.y + v.z * v.z + v.w * v.w;
    #pragma unroll
    for (int o = 16; o > 0; o >>= 1) {
        s  += __shfl_xor_sync(0xffffffffu, s,  o);
        ss += __shfl_xor_sync(0xffffffffu, ss, o);
    }
    __shared__ float sh[8][2];
    if ((t & 31) == 0) { sh[t >> 5][0] = s; sh[t >> 5][1] = ss; }
    __syncthreads();
    float ts = 0.f, tss = 0.f;
    #pragma unroll
    for (int i = 0; i < 8; i++) { ts += sh[i][0]; tss += sh[i][1]; }

    const float mu  = ts * (1.0f / Dd);
    const float var = tss * (1.0f / Dd) - mu * mu;
    const float inv = rsqrtf(var + LN_EPS);

    const float4 gg = ((const float4*)gamma)[t];
    const float4 bb = ((const float4*)beta)[t];
    float4 y;
    y.x = (v.x - mu) * inv * gg.x + bb.x;
    y.y = (v.y - mu) * inv * gg.y + bb.y;
    y.z = (v.z - mu) * inv * gg.z + bb.z;
    y.w = (v.w - mu) * inv * gg.w + bb.w;
    ((float4*)(Y + (size_t)row * Dd))[t] = y;
}

// ---------------------------------------------------------------------------
// Launch. Inputs: q, k, v, wq, wk, wv, wo, gamma, beta, mask (causal; unused).
// ---------------------------------------------------------------------------
extern "C" void kernel_launch(void* const* d_in, const int* in_sizes, int n_in,
                              void* d_out, int out_size)
{
    const float* q     = (const float*)d_in[0];
    const float* k     = (const float*)d_in[1];
    const float* v     = (const float*)d_in[2];
    const float* wq    = (const float*)d_in[3];
    const float* wk    = (const float*)d_in[4];
    const float* wv    = (const float*)d_in[5];
    const float* wo    = (const float*)d_in[6];
    const float* gamma = (const float*)d_in[7];
    const float* beta  = (const float*)d_in[8];
    float* out = (float*)d_out;

    float* gtmp;
    __nv_bfloat16 *gah, *gal, *gwh, *gwl;
    __nv_bfloat16 *gqh, *gql, *gkh, *gkl, *gvh, *gvl, *goh, *gol;
    cudaGetSymbolAddress((void**)&gtmp, g_tmp);
    cudaGetSymbolAddress((void**)&gah,  g_ah);
    cudaGetSymbolAddress((void**)&gal,  g_al);
    cudaGetSymbolAddress((void**)&gwh,  g_wh);
    cudaGetSymbolAddress((void**)&gwl,  g_wl);
    cudaGetSymbolAddress((void**)&gqh,  g_qh);
    cudaGetSymbolAddress((void**)&gql,  g_ql);
    cudaGetSymbolAddress((void**)&gkh,  g_kh);
    cudaGetSymbolAddress((void**)&gkl,  g_kl);
    cudaGetSymbolAddress((void**)&gvh,  g_vh);
    cudaGetSymbolAddress((void**)&gvl,  g_vl);
    cudaGetSymbolAddress((void**)&goh,  g_oh);
    cudaGetSymbolAddress((void**)&gol,  g_ol);

    cudaFuncSetAttribute(gemm_tc,
                         cudaFuncAttributeMaxDynamicSharedMemorySize, GEMM_SMEM);
    cudaFuncSetAttribute(attn_tc,
                         cudaFuncAttributeMaxDynamicSharedMemorySize, ATTN2_SMEM);

    const dim3 blk256(256);
    const dim3 blk128(128);
    const dim3 gconv(MS * Dd / 4 / 256);
    const dim3 gwt(Dd / 32, Dd / 32);
    const dim3 ggemm(Dd / 128, MS / 128);     // (8, 32)

    // Q projection -> split
    conv_wt<<<gwt, blk256>>>(wq, gwh, gwl);
    conv_act<<<gconv, blk256>>>(q, gah, gal);
    gemm_tc<<<ggemm, blk128, GEMM_SMEM>>>(gah, gal, gwh, gwl, nullptr, nullptr, gqh, gql);
    // K projection -> split
    conv_wt<<<gwt, blk256>>>(wk, gwh, gwl);
    conv_act<<<gconv, blk256>>>(k, gah, gal);
    gemm_tc<<<ggemm, blk128, GEMM_SMEM>>>(gah, gal, gwh, gwl, nullptr, nullptr, gkh, gkl);
    // V projection -> split
    conv_wt<<<gwt, blk256>>>(wv, gwh, gwl);
    conv_act<<<gconv, blk256>>>(v, gah, gal);
    gemm_tc<<<ggemm, blk128, GEMM_SMEM>>>(gah, gal, gwh, gwl, nullptr, nullptr, gvh, gvl);

    // flash attention (tensor cores) -> split output
    dim3 ga(Ss / 128, Hh, Bb);                // (16, 16, 2)
    attn_tc<<<ga, blk256, ATTN2_SMEM>>>(gqh, gql, gkh, gkl, gvh, gvl, goh, gol);

    // output projection + residual (fp32 out)
    conv_wt<<<gwt, blk256>>>(wo, gwh, gwl);
    gemm_tc<<<ggemm, blk128, GEMM_SMEM>>>(goh, gol, gwh, gwl, q, gtmp, nullptr, nullptr);

    // LayerNorm
    ln_kernel<<<MS, blk256>>>(gtmp, gamma, beta, out);
}